// round 12
// baseline (speedup 1.0000x reference)
#include <cuda_runtime.h>
#include <cuda_fp16.h>
#include <stdint.h>

#define N_NODES 100000
#define N_EDGES 1600000
#define F_IN  64
#define F_HID 64
#define F_OUT 32

#define SCAN_B 98   // 98 * 1024 >= N_NODES; single wave on 148 SMs

typedef unsigned long long ull;

// ---------------- static device scratch ----------------
__device__ float  g_dinv[N_NODES];
__device__ __half g_xws [N_NODES * F_HID];   // (x@W1)*dinv, fp16
__device__ float  g_h   [N_NODES * F_HID];   // relu hidden (fp32)
__device__ __half g_hws [N_NODES * F_OUT];   // (h@W2)*dinv, fp16
__device__ int    g_cnt [N_NODES];           // BSS-zero; re-zeroed each call
__device__ int    g_off [N_NODES + 1];
__device__ int    g_cur [N_NODES];
__device__ int    g_csr [N_EDGES];
__device__ int    g_scanval [SCAN_B];
__device__ int    g_scanflag[SCAN_B];
__device__ int    g_done;

// ---------------- packed f32x2 helpers ----------------
__device__ __forceinline__ ull pack2(float lo, float hi) {
    ull r; asm("mov.b64 %0, {%1, %2};" : "=l"(r) : "f"(lo), "f"(hi)); return r;
}
__device__ __forceinline__ void unpack2(ull v, float& lo, float& hi) {
    asm("mov.b64 {%0, %1}, %2;" : "=f"(lo), "=f"(hi) : "l"(v));
}
__device__ __forceinline__ ull fma2(ull a, ull b, ull c) {
    ull d; asm("fma.rn.f32x2 %0, %1, %2, %3;" : "=l"(d) : "l"(a), "l"(b), "l"(c)); return d;
}
__device__ __forceinline__ ull mul2(ull a, ull b) {
    ull d; asm("mul.rn.f32x2 %0, %1, %2;" : "=l"(d) : "l"(a), "l"(b)); return d;
}

// dtype detection: int64 layout (values<2^31) => odd words zero
__device__ __forceinline__ int detect64_t0(const int* __restrict__ w) {
    int nz = 0;
#pragma unroll
    for (int j = 1; j < 16; j += 2) nz |= w[j];
    return nz == 0;
}

// ---------------- histogram over dst ----------------
__global__ void k_hist(const int* __restrict__ ew) {
    __shared__ int s64;
    if (threadIdx.x == 0) s64 = detect64_t0(ew);
    __syncthreads();
    int e = blockIdx.x * blockDim.x + threadIdx.x;
    if (e >= N_EDGES) return;
    int d = s64 ? ew[2 * N_EDGES + 2 * e] : ew[N_EDGES + e];
    atomicAdd(&g_cnt[d], 1);
}

// ---------------- single-pass scan ----------------
__global__ void __launch_bounds__(1024) k_scan1() {
    int b = blockIdx.x, t = threadIdx.x;
    int i = b * 1024 + t;
    int lane = t & 31, wid = t >> 5;
    int c = (i < N_NODES) ? g_cnt[i] : 0;

    int inc = c;
#pragma unroll
    for (int o = 1; o < 32; o <<= 1) {
        int u = __shfl_up_sync(0xffffffffu, inc, o);
        if (lane >= o) inc += u;
    }
    __shared__ int wpre[32];
    __shared__ int s_base;
    if (lane == 31) wpre[wid] = inc;
    __syncthreads();

    if (wid == 0) {
        int s = wpre[lane];
        int sinc = s;
#pragma unroll
        for (int o = 1; o < 32; o <<= 1) {
            int u = __shfl_up_sync(0xffffffffu, sinc, o);
            if (lane >= o) sinc += u;
        }
        wpre[lane] = sinc - s;
        if (lane == 31) {
            g_scanval[b] = sinc;
            __threadfence();
            atomicExch(&g_scanflag[b], 1);
        }
    } else if (wid == 1) {
        int base = 0;
        for (int j = lane; j < b; j += 32) {
            while (atomicAdd(&g_scanflag[j], 0) == 0) {}
            __threadfence();
            base += *((volatile int*)(g_scanval + j));
        }
#pragma unroll
        for (int o = 16; o > 0; o >>= 1)
            base += __shfl_down_sync(0xffffffffu, base, o);
        if (lane == 0) s_base = base;
    }
    __syncthreads();

    if (i < N_NODES) {
        int exc = inc - c + wpre[wid] + s_base;
        g_off[i] = exc;
        g_cur[i] = exc;
        g_dinv[i] = rsqrtf((float)c + 1.0f);
        g_cnt[i] = 0;
    }
    if (b == 0 && t == 0) g_off[N_NODES] = N_EDGES;

    __syncthreads();
    if (t == 0) {
        __threadfence();
        int d = atomicAdd(&g_done, 1);
        if (d == gridDim.x - 1) {
            for (int j = 0; j < SCAN_B; j++) g_scanflag[j] = 0;
            g_done = 0;
            __threadfence();
        }
    }
}

// ---------------- fill CSR ----------------
__global__ void k_fill(const int* __restrict__ ew) {
    __shared__ int s64;
    if (threadIdx.x == 0) s64 = detect64_t0(ew);
    __syncthreads();
    int e = blockIdx.x * blockDim.x + threadIdx.x;
    if (e >= N_EDGES) return;
    int s, d;
    if (s64) {
        s = ew[2 * e];
        d = ew[2 * N_EDGES + 2 * e];
    } else {
        s = ew[e];
        d = ew[N_EDGES + e];
    }
    int slot = atomicAdd(&g_cur[d], 1);
    g_csr[slot] = s;
}

// ---------------- GEMM1: register-tiled RM=2 x RN=16, f32x2, occ>=3 blocks ----
// block covers 128 rows; rg=tid>>2 (64 row-pairs), cg=tid&3 (16-col group)
__global__ void __launch_bounds__(256, 3) k_gemm1(const float* __restrict__ x,
                                                  const float* __restrict__ W) {
    __shared__ float4 ws[F_IN][F_HID / 4];  // 16KB = 1024 float4
    int tid = threadIdx.x;
#pragma unroll
    for (int i = 0; i < 4; i++)
        ((float4*)ws)[tid + i * 256] = ((const float4*)W)[tid + i * 256];
    __syncthreads();

    int rg = tid >> 2, cg = tid & 3;
    int row0 = blockIdx.x * 128 + rg * 2;
    if (row0 >= N_NODES) return;
    int r1 = min(row0 + 1, N_NODES - 1);

    ull acc[2][8];
#pragma unroll
    for (int i = 0; i < 2; i++)
#pragma unroll
        for (int j = 0; j < 8; j++) acc[i][j] = 0ull;

#pragma unroll 4
    for (int kk = 0; kk < 16; kk++) {
        float4 xv0 = __ldg((const float4*)(x + (size_t)row0 * F_IN) + kk);
        float4 xv1 = __ldg((const float4*)(x + (size_t)r1 * F_IN) + kk);
        float xs[2][4] = {{xv0.x, xv0.y, xv0.z, xv0.w},
                          {xv1.x, xv1.y, xv1.z, xv1.w}};
#pragma unroll
        for (int t = 0; t < 4; t++) {
            int k = kk * 4 + t;
            ull wp[8];
#pragma unroll
            for (int j = 0; j < 4; j++) {
                float4 w4 = ws[k][cg * 4 + j];
                wp[2 * j]     = pack2(w4.x, w4.y);
                wp[2 * j + 1] = pack2(w4.z, w4.w);
            }
#pragma unroll
            for (int i = 0; i < 2; i++) {
                ull xk2 = pack2(xs[i][t], xs[i][t]);
#pragma unroll
                for (int j = 0; j < 8; j++)
                    acc[i][j] = fma2(xk2, wp[j], acc[i][j]);
            }
        }
    }

#pragma unroll
    for (int i = 0; i < 2; i++) {
        int row = row0 + i;
        if (row >= N_NODES) break;
        float s = g_dinv[row];
        ull s2 = pack2(s, s);
        __half2 hrow[8];
#pragma unroll
        for (int j = 0; j < 8; j++) {
            float lo, hi;
            unpack2(mul2(acc[i][j], s2), lo, hi);
            hrow[j] = __floats2half2_rn(lo, hi);
        }
        uint4* o = (uint4*)(g_xws + (size_t)row * F_HID + cg * 16);
        const uint4* hp = (const uint4*)hrow;
        o[0] = hp[0];
        o[1] = hp[1];
    }
}

// ---------------- aggregate layer 1 + hidden epilogue (warp per node) ----------
__global__ void __launch_bounds__(256) k_agg1(const float* __restrict__ b1) {
    int node = (blockIdx.x * 256 + threadIdx.x) >> 5;
    int lane = threadIdx.x & 31;
    if (node >= N_NODES) return;

    int k   = g_off[node];
    int end = g_off[node + 1];
    int col = lane * 2;

    float2 acc0 = make_float2(0.f, 0.f);
    float2 acc1 = make_float2(0.f, 0.f);

    for (; k + 8 <= end; k += 8) {
        int idx[8];
#pragma unroll
        for (int j = 0; j < 8; j++) idx[j] = __ldg(g_csr + k + j);
        __half2 v[8];
#pragma unroll
        for (int j = 0; j < 8; j++)
            v[j] = *(const __half2*)(g_xws + (size_t)idx[j] * F_HID + col);
#pragma unroll
        for (int j = 0; j < 8; j += 2) {
            float2 f0 = __half22float2(v[j]);
            float2 f1 = __half22float2(v[j + 1]);
            acc0.x += f0.x; acc0.y += f0.y;
            acc1.x += f1.x; acc1.y += f1.y;
        }
    }
    for (; k < end; k++) {
        int s = __ldg(g_csr + k);
        float2 f = __half22float2(*(const __half2*)(g_xws + (size_t)s * F_HID + col));
        acc0.x += f.x; acc0.y += f.y;
    }

    float2 self = __half22float2(*(const __half2*)(g_xws + (size_t)node * F_HID + col));
    float sc = g_dinv[node];
    float2 b = ((const float2*)b1)[lane];
    float2 r;
    r.x = fmaxf(sc * (acc0.x + acc1.x + self.x) + b.x, 0.f);
    r.y = fmaxf(sc * (acc0.y + acc1.y + self.y) + b.y, 0.f);
    *(float2*)(g_h + (size_t)node * F_HID + col) = r;
}

// ---------------- GEMM2: register-tiled RM=2 x RN=16, f32x2 ----------------
// block covers 256 rows; rg=tid>>1 (128 row-pairs), cg=tid&1
__global__ void __launch_bounds__(256, 3) k_gemm2(const float* __restrict__ W) {
    __shared__ float4 ws[F_HID][F_OUT / 4];  // 8KB = 512 float4
    int tid = threadIdx.x;
#pragma unroll
    for (int i = 0; i < 2; i++)
        ((float4*)ws)[tid + i * 256] = ((const float4*)W)[tid + i * 256];
    __syncthreads();

    int rg = tid >> 1, cg = tid & 1;
    int row0 = blockIdx.x * 256 + rg * 2;   // 128 row-pairs = 256 rows/block
    if (row0 >= N_NODES) return;
    int r1 = min(row0 + 1, N_NODES - 1);

    ull acc[2][8];
#pragma unroll
    for (int i = 0; i < 2; i++)
#pragma unroll
        for (int j = 0; j < 8; j++) acc[i][j] = 0ull;

#pragma unroll 4
    for (int kk = 0; kk < 16; kk++) {
        float4 hv0 = __ldg((const float4*)(g_h + (size_t)row0 * F_HID) + kk);
        float4 hv1 = __ldg((const float4*)(g_h + (size_t)r1 * F_HID) + kk);
        float hs[2][4] = {{hv0.x, hv0.y, hv0.z, hv0.w},
                          {hv1.x, hv1.y, hv1.z, hv1.w}};
#pragma unroll
        for (int t = 0; t < 4; t++) {
            int k = kk * 4 + t;
            ull wp[8];
#pragma unroll
            for (int j = 0; j < 4; j++) {
                float4 w4 = ws[k][cg * 4 + j];
                wp[2 * j]     = pack2(w4.x, w4.y);
                wp[2 * j + 1] = pack2(w4.z, w4.w);
            }
#pragma unroll
            for (int i = 0; i < 2; i++) {
                ull hk2 = pack2(hs[i][t], hs[i][t]);
#pragma unroll
                for (int j = 0; j < 8; j++)
                    acc[i][j] = fma2(hk2, wp[j], acc[i][j]);
            }
        }
    }

#pragma unroll
    for (int i = 0; i < 2; i++) {
        int row = row0 + i;
        if (row >= N_NODES) break;
        float s = g_dinv[row];
        ull s2 = pack2(s, s);
        __half2 hrow[8];
#pragma unroll
        for (int j = 0; j < 8; j++) {
            float lo, hi;
            unpack2(mul2(acc[i][j], s2), lo, hi);
            hrow[j] = __floats2half2_rn(lo, hi);
        }
        uint4* o = (uint4*)(g_hws + (size_t)row * F_OUT + cg * 16);
        const uint4* hp = (const uint4*)hrow;
        o[0] = hp[0];
        o[1] = hp[1];
    }
}

// ---------------- aggregate layer 2 + output epilogue (warp per node) ----------
__global__ void __launch_bounds__(256) k_agg2(const float* __restrict__ b2,
                                              float* __restrict__ out) {
    int node = (blockIdx.x * 256 + threadIdx.x) >> 5;
    int lane = threadIdx.x & 31;
    if (node >= N_NODES) return;

    int k   = g_off[node];
    int end = g_off[node + 1];

    float acc0 = 0.f, acc1 = 0.f;

    for (; k + 8 <= end; k += 8) {
        int idx[8];
#pragma unroll
        for (int j = 0; j < 8; j++) idx[j] = __ldg(g_csr + k + j);
        float v[8];
#pragma unroll
        for (int j = 0; j < 8; j++)
            v[j] = __half2float(g_hws[(size_t)idx[j] * F_OUT + lane]);
        acc0 += (v[0] + v[2]) + (v[4] + v[6]);
        acc1 += (v[1] + v[3]) + (v[5] + v[7]);
    }
    for (; k < end; k++) {
        int s = __ldg(g_csr + k);
        acc0 += __half2float(g_hws[(size_t)s * F_OUT + lane]);
    }

    float self = __half2float(g_hws[(size_t)node * F_OUT + lane]);
    float sc = g_dinv[node];
    out[(size_t)node * F_OUT + lane] = sc * (acc0 + acc1 + self) + b2[lane];
}

// ---------------- launch ----------------
extern "C" void kernel_launch(void* const* d_in, const int* in_sizes, int n_in,
                              void* d_out, int out_size) {
    const float* x  = (const float*)d_in[0];
    const int*   ew = (const int*)d_in[1];
    const float* W1 = (const float*)d_in[2];
    const float* b1 = (const float*)d_in[3];
    const float* W2 = (const float*)d_in[4];
    const float* b2 = (const float*)d_in[5];
    float* out = (float*)d_out;

    const int T = 256;

    k_hist<<<(N_EDGES + T - 1) / T, T>>>(ew);
    k_scan1<<<SCAN_B, 1024>>>();
    k_fill<<<(N_EDGES + T - 1) / T, T>>>(ew);

    k_gemm1<<<(N_NODES + 127) / 128, T>>>(x, W1);
    k_agg1<<<(N_NODES * 32 + T - 1) / T, T>>>(b1);

    k_gemm2<<<(N_NODES + 255) / 256, T>>>(W2);
    k_agg2<<<(N_NODES * 32 + T - 1) / T, T>>>(b2, out);
}

// round 13
// speedup vs baseline: 1.1349x; 1.1349x over previous
#include <cuda_runtime.h>
#include <cuda_fp16.h>
#include <mma.h>
#include <stdint.h>

using namespace nvcuda;

#define N_NODES 100000
#define N_EDGES 1600000
#define F_IN  64
#define F_HID 64
#define F_OUT 32

#define SCAN_B 98   // 98 * 1024 >= N_NODES; single wave on 148 SMs

// ---------------- static device scratch ----------------
__device__ float  g_dinv[N_NODES];
__device__ __half g_xws [N_NODES * F_HID];   // (x@W1)*dinv, fp16
__device__ float  g_h   [N_NODES * F_HID];   // relu hidden (fp32)
__device__ __half g_hws [N_NODES * F_OUT];   // (h@W2)*dinv, fp16
__device__ int    g_cnt [N_NODES];           // BSS-zero; re-zeroed each call
__device__ int    g_off [N_NODES + 1];
__device__ int    g_cur [N_NODES];
__device__ int    g_csr [N_EDGES];
__device__ int    g_scanval [SCAN_B];
__device__ int    g_scanflag[SCAN_B];
__device__ int    g_done;

// dtype detection: int64 layout (values<2^31) => odd words zero
__device__ __forceinline__ int detect64_t0(const int* __restrict__ w) {
    int nz = 0;
#pragma unroll
    for (int j = 1; j < 16; j += 2) nz |= w[j];
    return nz == 0;
}

// ---------------- histogram over dst ----------------
__global__ void k_hist(const int* __restrict__ ew) {
    __shared__ int s64;
    if (threadIdx.x == 0) s64 = detect64_t0(ew);
    __syncthreads();
    int e = blockIdx.x * blockDim.x + threadIdx.x;
    if (e >= N_EDGES) return;
    int d = s64 ? ew[2 * N_EDGES + 2 * e] : ew[N_EDGES + e];
    atomicAdd(&g_cnt[d], 1);
}

// ---------------- single-pass scan ----------------
__global__ void __launch_bounds__(1024) k_scan1() {
    int b = blockIdx.x, t = threadIdx.x;
    int i = b * 1024 + t;
    int lane = t & 31, wid = t >> 5;
    int c = (i < N_NODES) ? g_cnt[i] : 0;

    int inc = c;
#pragma unroll
    for (int o = 1; o < 32; o <<= 1) {
        int u = __shfl_up_sync(0xffffffffu, inc, o);
        if (lane >= o) inc += u;
    }
    __shared__ int wpre[32];
    __shared__ int s_base;
    if (lane == 31) wpre[wid] = inc;
    __syncthreads();

    if (wid == 0) {
        int s = wpre[lane];
        int sinc = s;
#pragma unroll
        for (int o = 1; o < 32; o <<= 1) {
            int u = __shfl_up_sync(0xffffffffu, sinc, o);
            if (lane >= o) sinc += u;
        }
        wpre[lane] = sinc - s;
        if (lane == 31) {
            g_scanval[b] = sinc;
            __threadfence();
            atomicExch(&g_scanflag[b], 1);
        }
    } else if (wid == 1) {
        int base = 0;
        for (int j = lane; j < b; j += 32) {
            while (atomicAdd(&g_scanflag[j], 0) == 0) {}
            __threadfence();
            base += *((volatile int*)(g_scanval + j));
        }
#pragma unroll
        for (int o = 16; o > 0; o >>= 1)
            base += __shfl_down_sync(0xffffffffu, base, o);
        if (lane == 0) s_base = base;
    }
    __syncthreads();

    if (i < N_NODES) {
        int exc = inc - c + wpre[wid] + s_base;
        g_off[i] = exc;
        g_cur[i] = exc;
        g_dinv[i] = rsqrtf((float)c + 1.0f);
        g_cnt[i] = 0;
    }
    if (b == 0 && t == 0) g_off[N_NODES] = N_EDGES;

    __syncthreads();
    if (t == 0) {
        __threadfence();
        int d = atomicAdd(&g_done, 1);
        if (d == gridDim.x - 1) {
            for (int j = 0; j < SCAN_B; j++) g_scanflag[j] = 0;
            g_done = 0;
            __threadfence();
        }
    }
}

// ---------------- fill CSR ----------------
__global__ void k_fill(const int* __restrict__ ew) {
    __shared__ int s64;
    if (threadIdx.x == 0) s64 = detect64_t0(ew);
    __syncthreads();
    int e = blockIdx.x * blockDim.x + threadIdx.x;
    if (e >= N_EDGES) return;
    int s, d;
    if (s64) {
        s = ew[2 * e];
        d = ew[2 * N_EDGES + 2 * e];
    } else {
        s = ew[e];
        d = ew[N_EDGES + e];
    }
    int slot = atomicAdd(&g_cur[d], 1);
    g_csr[slot] = s;
}

// ---------------- GEMM1 (wmma tf32): xws = fp16((x @ W1) * dinv) ----------------
// 8 warps/block, each warp a 16x64 tile; block = 128 rows
__global__ void __launch_bounds__(256) k_gemm1(const float* __restrict__ x,
                                               const float* __restrict__ W) {
    __shared__ float wsm[F_IN * F_HID];        // 16KB, tf32-converted
    __shared__ float obuf[8 * 16 * F_HID];     // 32KB epilogue staging
    int tid = threadIdx.x;
    for (int i = tid; i < F_IN * F_HID; i += 256)
        wsm[i] = wmma::__float_to_tf32(W[i]);
    __syncthreads();

    int warp = tid >> 5, lane = tid & 31;
    int row0 = blockIdx.x * 128 + warp * 16;
    int rowc = min(row0, N_NODES - 16);    // clamp tail; duplicate rows benign

    wmma::fragment<wmma::accumulator, 16, 16, 8, float> acc[4];
#pragma unroll
    for (int n = 0; n < 4; n++) wmma::fill_fragment(acc[n], 0.0f);

#pragma unroll
    for (int k = 0; k < 8; k++) {
        wmma::fragment<wmma::matrix_a, 16, 16, 8, wmma::precision::tf32,
                       wmma::row_major> a;
        wmma::load_matrix_sync(a, x + (size_t)rowc * F_IN + k * 8, F_IN);
#pragma unroll
        for (int i = 0; i < a.num_elements; i++)
            a.x[i] = wmma::__float_to_tf32(a.x[i]);
#pragma unroll
        for (int n = 0; n < 4; n++) {
            wmma::fragment<wmma::matrix_b, 16, 16, 8, wmma::precision::tf32,
                           wmma::row_major> bfr;
            wmma::load_matrix_sync(bfr, wsm + k * 8 * F_HID + n * 16, F_HID);
            wmma::mma_sync(acc[n], a, bfr, acc[n]);
        }
    }

    float* my = obuf + warp * 16 * F_HID;
#pragma unroll
    for (int n = 0; n < 4; n++)
        wmma::store_matrix_sync(my + n * 16, acc[n], F_HID, wmma::mem_row_major);
    __syncwarp();

    // scale by dinv, pack fp16, coalesced half2 stores
#pragma unroll
    for (int i = 0; i < 16; i++) {
        int e = lane + i * 32;      // 0..511 (512 half2 in 16x64 tile)
        int r = e >> 5;             // 32 half2 per row
        int c = e & 31;
        int row = rowc + r;
        float s = g_dinv[row];
        float lo = my[r * F_HID + c * 2]     * s;
        float hi = my[r * F_HID + c * 2 + 1] * s;
        *(__half2*)(g_xws + (size_t)row * F_HID + c * 2) = __floats2half2_rn(lo, hi);
    }
}

// ---------------- aggregate layer 1 + hidden epilogue (warp per node) ----------
__global__ void __launch_bounds__(256) k_agg1(const float* __restrict__ b1) {
    int node = (blockIdx.x * 256 + threadIdx.x) >> 5;
    int lane = threadIdx.x & 31;
    if (node >= N_NODES) return;

    int k   = g_off[node];
    int end = g_off[node + 1];
    int col = lane * 2;

    float2 acc0 = make_float2(0.f, 0.f);
    float2 acc1 = make_float2(0.f, 0.f);

    for (; k + 8 <= end; k += 8) {
        int idx[8];
#pragma unroll
        for (int j = 0; j < 8; j++) idx[j] = __ldg(g_csr + k + j);
        __half2 v[8];
#pragma unroll
        for (int j = 0; j < 8; j++)
            v[j] = *(const __half2*)(g_xws + (size_t)idx[j] * F_HID + col);
#pragma unroll
        for (int j = 0; j < 8; j += 2) {
            float2 f0 = __half22float2(v[j]);
            float2 f1 = __half22float2(v[j + 1]);
            acc0.x += f0.x; acc0.y += f0.y;
            acc1.x += f1.x; acc1.y += f1.y;
        }
    }
    for (; k < end; k++) {
        int s = __ldg(g_csr + k);
        float2 f = __half22float2(*(const __half2*)(g_xws + (size_t)s * F_HID + col));
        acc0.x += f.x; acc0.y += f.y;
    }

    float2 self = __half22float2(*(const __half2*)(g_xws + (size_t)node * F_HID + col));
    float sc = g_dinv[node];
    float2 b = ((const float2*)b1)[lane];
    float2 r;
    r.x = fmaxf(sc * (acc0.x + acc1.x + self.x) + b.x, 0.f);
    r.y = fmaxf(sc * (acc0.y + acc1.y + self.y) + b.y, 0.f);
    *(float2*)(g_h + (size_t)node * F_HID + col) = r;
}

// ---------------- GEMM2 (wmma tf32): hws = fp16((h @ W2) * dinv) ----------------
// 8 warps/block, each warp a 16x32 tile; block = 128 rows
__global__ void __launch_bounds__(256) k_gemm2(const float* __restrict__ W) {
    __shared__ float wsm[F_HID * F_OUT];       // 8KB, tf32-converted
    __shared__ float obuf[8 * 16 * F_OUT];     // 16KB
    int tid = threadIdx.x;
    for (int i = tid; i < F_HID * F_OUT; i += 256)
        wsm[i] = wmma::__float_to_tf32(W[i]);
    __syncthreads();

    int warp = tid >> 5, lane = tid & 31;
    int row0 = blockIdx.x * 128 + warp * 16;
    int rowc = min(row0, N_NODES - 16);

    wmma::fragment<wmma::accumulator, 16, 16, 8, float> acc[2];
#pragma unroll
    for (int n = 0; n < 2; n++) wmma::fill_fragment(acc[n], 0.0f);

#pragma unroll
    for (int k = 0; k < 8; k++) {
        wmma::fragment<wmma::matrix_a, 16, 16, 8, wmma::precision::tf32,
                       wmma::row_major> a;
        wmma::load_matrix_sync(a, g_h + (size_t)rowc * F_HID + k * 8, F_HID);
#pragma unroll
        for (int i = 0; i < a.num_elements; i++)
            a.x[i] = wmma::__float_to_tf32(a.x[i]);
#pragma unroll
        for (int n = 0; n < 2; n++) {
            wmma::fragment<wmma::matrix_b, 16, 16, 8, wmma::precision::tf32,
                           wmma::row_major> bfr;
            wmma::load_matrix_sync(bfr, wsm + k * 8 * F_OUT + n * 16, F_OUT);
            wmma::mma_sync(acc[n], a, bfr, acc[n]);
        }
    }

    float* my = obuf + warp * 16 * F_OUT;
#pragma unroll
    for (int n = 0; n < 2; n++)
        wmma::store_matrix_sync(my + n * 16, acc[n], F_OUT, wmma::mem_row_major);
    __syncwarp();

#pragma unroll
    for (int i = 0; i < 8; i++) {
        int e = lane + i * 32;      // 0..255 (256 half2 in 16x32 tile)
        int r = e >> 4;             // 16 half2 per row
        int c = e & 15;
        int row = rowc + r;
        float s = g_dinv[row];
        float lo = my[r * F_OUT + c * 2]     * s;
        float hi = my[r * F_OUT + c * 2 + 1] * s;
        *(__half2*)(g_hws + (size_t)row * F_OUT + c * 2) = __floats2half2_rn(lo, hi);
    }
}

// ---------------- aggregate layer 2 + output epilogue (warp per node) ----------
__global__ void __launch_bounds__(256) k_agg2(const float* __restrict__ b2,
                                              float* __restrict__ out) {
    int node = (blockIdx.x * 256 + threadIdx.x) >> 5;
    int lane = threadIdx.x & 31;
    if (node >= N_NODES) return;

    int k   = g_off[node];
    int end = g_off[node + 1];

    float acc0 = 0.f, acc1 = 0.f;

    for (; k + 8 <= end; k += 8) {
        int idx[8];
#pragma unroll
        for (int j = 0; j < 8; j++) idx[j] = __ldg(g_csr + k + j);
        float v[8];
#pragma unroll
        for (int j = 0; j < 8; j++)
            v[j] = __half2float(g_hws[(size_t)idx[j] * F_OUT + lane]);
        acc0 += (v[0] + v[2]) + (v[4] + v[6]);
        acc1 += (v[1] + v[3]) + (v[5] + v[7]);
    }
    for (; k < end; k++) {
        int s = __ldg(g_csr + k);
        acc0 += __half2float(g_hws[(size_t)s * F_OUT + lane]);
    }

    float self = __half2float(g_hws[(size_t)node * F_OUT + lane]);
    float sc = g_dinv[node];
    out[(size_t)node * F_OUT + lane] = sc * (acc0 + acc1 + self) + b2[lane];
}

// ---------------- launch ----------------
extern "C" void kernel_launch(void* const* d_in, const int* in_sizes, int n_in,
                              void* d_out, int out_size) {
    const float* x  = (const float*)d_in[0];
    const int*   ew = (const int*)d_in[1];
    const float* W1 = (const float*)d_in[2];
    const float* b1 = (const float*)d_in[3];
    const float* W2 = (const float*)d_in[4];
    const float* b2 = (const float*)d_in[5];
    float* out = (float*)d_out;

    const int T = 256;

    k_hist<<<(N_EDGES + T - 1) / T, T>>>(ew);
    k_scan1<<<SCAN_B, 1024>>>();
    k_fill<<<(N_EDGES + T - 1) / T, T>>>(ew);

    k_gemm1<<<(N_NODES + 127) / 128, T>>>(x, W1);
    k_agg1<<<(N_NODES * 32 + T - 1) / T, T>>>(b1);

    k_gemm2<<<(N_NODES + 127) / 128, T>>>(W2);
    k_agg2<<<(N_NODES * 32 + T - 1) / T, T>>>(b2, out);
}

// round 14
// speedup vs baseline: 1.2755x; 1.1238x over previous
#include <cuda_runtime.h>
#include <cuda_fp16.h>
#include <mma.h>
#include <stdint.h>

using namespace nvcuda;

#define N_NODES 100000
#define N_EDGES 1600000
#define F_IN  64
#define F_HID 64
#define F_OUT 32

#define SCAN_B 98   // 98 * 1024 >= N_NODES; single wave on 148 SMs

// ---------------- static device scratch ----------------
__device__ float  g_dinv[N_NODES];
__device__ __half g_xws [N_NODES * F_HID];   // (x@W1)*dinv, fp16
__device__ float  g_h   [N_NODES * F_HID];   // relu hidden (fp32)
__device__ __half g_hws [N_NODES * F_OUT];   // (h@W2)*dinv, fp16
__device__ int    g_cnt [N_NODES];           // BSS-zero; re-zeroed each call
__device__ int    g_off [N_NODES + 1];
__device__ int    g_cur [N_NODES];
__device__ int    g_csr [N_EDGES];
__device__ int    g_scanval [SCAN_B];
__device__ int    g_scanflag[SCAN_B];
__device__ int    g_done;

// dtype detection: int64 layout (values<2^31) => odd words zero
__device__ __forceinline__ int detect64_t0(const int* __restrict__ w) {
    int nz = 0;
#pragma unroll
    for (int j = 1; j < 16; j += 2) nz |= w[j];
    return nz == 0;
}

// ---------------- histogram over dst ----------------
__global__ void k_hist(const int* __restrict__ ew) {
    __shared__ int s64;
    if (threadIdx.x == 0) s64 = detect64_t0(ew);
    __syncthreads();
    int e = blockIdx.x * blockDim.x + threadIdx.x;
    if (e >= N_EDGES) return;
    int d = s64 ? ew[2 * N_EDGES + 2 * e] : ew[N_EDGES + e];
    atomicAdd(&g_cnt[d], 1);
}

// ---------------- single-pass scan ----------------
__global__ void __launch_bounds__(1024) k_scan1() {
    int b = blockIdx.x, t = threadIdx.x;
    int i = b * 1024 + t;
    int lane = t & 31, wid = t >> 5;
    int c = (i < N_NODES) ? g_cnt[i] : 0;

    int inc = c;
#pragma unroll
    for (int o = 1; o < 32; o <<= 1) {
        int u = __shfl_up_sync(0xffffffffu, inc, o);
        if (lane >= o) inc += u;
    }
    __shared__ int wpre[32];
    __shared__ int s_base;
    if (lane == 31) wpre[wid] = inc;
    __syncthreads();

    if (wid == 0) {
        int s = wpre[lane];
        int sinc = s;
#pragma unroll
        for (int o = 1; o < 32; o <<= 1) {
            int u = __shfl_up_sync(0xffffffffu, sinc, o);
            if (lane >= o) sinc += u;
        }
        wpre[lane] = sinc - s;
        if (lane == 31) {
            g_scanval[b] = sinc;
            __threadfence();
            atomicExch(&g_scanflag[b], 1);
        }
    } else if (wid == 1) {
        int base = 0;
        for (int j = lane; j < b; j += 32) {
            while (atomicAdd(&g_scanflag[j], 0) == 0) {}
            __threadfence();
            base += *((volatile int*)(g_scanval + j));
        }
#pragma unroll
        for (int o = 16; o > 0; o >>= 1)
            base += __shfl_down_sync(0xffffffffu, base, o);
        if (lane == 0) s_base = base;
    }
    __syncthreads();

    if (i < N_NODES) {
        int exc = inc - c + wpre[wid] + s_base;
        g_off[i] = exc;
        g_cur[i] = exc;
        g_dinv[i] = rsqrtf((float)c + 1.0f);
        g_cnt[i] = 0;
    }
    if (b == 0 && t == 0) g_off[N_NODES] = N_EDGES;

    __syncthreads();
    if (t == 0) {
        __threadfence();
        int d = atomicAdd(&g_done, 1);
        if (d == gridDim.x - 1) {
            for (int j = 0; j < SCAN_B; j++) g_scanflag[j] = 0;
            g_done = 0;
            __threadfence();
        }
    }
}

// ---------------- fill CSR ----------------
__global__ void k_fill(const int* __restrict__ ew) {
    __shared__ int s64;
    if (threadIdx.x == 0) s64 = detect64_t0(ew);
    __syncthreads();
    int e = blockIdx.x * blockDim.x + threadIdx.x;
    if (e >= N_EDGES) return;
    int s, d;
    if (s64) {
        s = ew[2 * e];
        d = ew[2 * N_EDGES + 2 * e];
    } else {
        s = ew[e];
        d = ew[N_EDGES + e];
    }
    int slot = atomicAdd(&g_cur[d], 1);
    g_csr[slot] = s;
}

// ---------------- GEMM1 (wmma fp16 m16n16k16): xws = fp16((x @ W1) * dinv) -----
// 8 warps/block, each warp a 16x64 tile; block = 128 rows
#define LDX1 72   // padded half ldm for A tile
#define LDW1 72   // padded half ldm for W1
#define LDO1 68   // padded float ldm for epilogue
__global__ void __launch_bounds__(256) k_gemm1(const float* __restrict__ x,
                                               const float* __restrict__ W) {
    __shared__ __half wh[F_IN * LDW1];                 // 9216 B
    __shared__ float obuf[128 * LDO1];                 // 34816 B (aliases xh)
    __half* xh = (__half*)obuf;                        // 128*LDX1 halves = 18432 B

    int tid = threadIdx.x;
    int rowb = min(blockIdx.x * 128, N_NODES - 128);   // clamped block base

    // stage W1 (64x64) -> half, padded
    for (int i = tid; i < F_IN * (F_HID / 2); i += 256) {
        int r = i >> 5, cp = i & 31;
        float2 w2 = *(const float2*)(W + r * F_HID + cp * 2);
        *(__half2*)(wh + r * LDW1 + cp * 2) = __floats2half2_rn(w2.x, w2.y);
    }
    // stage x tile (128x64) -> half, padded
    for (int i = tid; i < 128 * (F_IN / 2); i += 256) {
        int r = i >> 5, cp = i & 31;
        float2 x2 = *(const float2*)(x + (size_t)(rowb + r) * F_IN + cp * 2);
        *(__half2*)(xh + r * LDX1 + cp * 2) = __floats2half2_rn(x2.x, x2.y);
    }
    __syncthreads();

    int warp = tid >> 5, lane = tid & 31;

    wmma::fragment<wmma::accumulator, 16, 16, 16, float> acc[4];
#pragma unroll
    for (int n = 0; n < 4; n++) wmma::fill_fragment(acc[n], 0.0f);

#pragma unroll
    for (int k = 0; k < 4; k++) {
        wmma::fragment<wmma::matrix_a, 16, 16, 16, __half, wmma::row_major> a;
        wmma::load_matrix_sync(a, xh + (warp * 16) * LDX1 + k * 16, LDX1);
#pragma unroll
        for (int n = 0; n < 4; n++) {
            wmma::fragment<wmma::matrix_b, 16, 16, 16, __half, wmma::row_major> bf;
            wmma::load_matrix_sync(bf, wh + (k * 16) * LDW1 + n * 16, LDW1);
            wmma::mma_sync(acc[n], a, bf, acc[n]);
        }
    }
    __syncthreads();   // xh reads complete before obuf overwrite

    float* my = obuf + warp * 16 * LDO1;
#pragma unroll
    for (int n = 0; n < 4; n++)
        wmma::store_matrix_sync(my + n * 16, acc[n], LDO1, wmma::mem_row_major);
    __syncwarp();

    // scale by dinv, pack fp16, coalesced half2 stores
#pragma unroll
    for (int r = 0; r < 16; r++) {
        int row = rowb + warp * 16 + r;
        float s = g_dinv[row];
        float lo = my[r * LDO1 + lane * 2]     * s;
        float hi = my[r * LDO1 + lane * 2 + 1] * s;
        *(__half2*)(g_xws + (size_t)row * F_HID + lane * 2) = __floats2half2_rn(lo, hi);
    }
}

// ---------------- aggregate layer 1 + hidden epilogue (warp per node) ----------
__global__ void __launch_bounds__(256) k_agg1(const float* __restrict__ b1) {
    int node = (blockIdx.x * 256 + threadIdx.x) >> 5;
    int lane = threadIdx.x & 31;
    if (node >= N_NODES) return;

    int k   = g_off[node];
    int end = g_off[node + 1];
    int col = lane * 2;

    float2 acc0 = make_float2(0.f, 0.f);
    float2 acc1 = make_float2(0.f, 0.f);

    for (; k + 8 <= end; k += 8) {
        int idx[8];
#pragma unroll
        for (int j = 0; j < 8; j++) idx[j] = __ldg(g_csr + k + j);
        __half2 v[8];
#pragma unroll
        for (int j = 0; j < 8; j++)
            v[j] = *(const __half2*)(g_xws + (size_t)idx[j] * F_HID + col);
#pragma unroll
        for (int j = 0; j < 8; j += 2) {
            float2 f0 = __half22float2(v[j]);
            float2 f1 = __half22float2(v[j + 1]);
            acc0.x += f0.x; acc0.y += f0.y;
            acc1.x += f1.x; acc1.y += f1.y;
        }
    }
    for (; k < end; k++) {
        int s = __ldg(g_csr + k);
        float2 f = __half22float2(*(const __half2*)(g_xws + (size_t)s * F_HID + col));
        acc0.x += f.x; acc0.y += f.y;
    }

    float2 self = __half22float2(*(const __half2*)(g_xws + (size_t)node * F_HID + col));
    float sc = g_dinv[node];
    float2 b = ((const float2*)b1)[lane];
    float2 r;
    r.x = fmaxf(sc * (acc0.x + acc1.x + self.x) + b.x, 0.f);
    r.y = fmaxf(sc * (acc0.y + acc1.y + self.y) + b.y, 0.f);
    *(float2*)(g_h + (size_t)node * F_HID + col) = r;
}

// ---------------- GEMM2 (wmma fp16): hws = fp16((h @ W2) * dinv) ----------------
#define LDX2 72   // padded half ldm for A tile
#define LDW2 40   // padded half ldm for W2
#define LDO2 36   // padded float ldm for epilogue
__global__ void __launch_bounds__(256) k_gemm2(const float* __restrict__ W) {
    __shared__ __half wh[F_HID * LDW2];                // 5120 B
    __shared__ float obuf[128 * LDO2];                 // 18432 B (aliases hh)
    __half* hh = (__half*)obuf;                        // 128*LDX2 halves = 18432 B

    int tid = threadIdx.x;
    int rowb = min(blockIdx.x * 128, N_NODES - 128);

    // stage W2 (64x32) -> half, padded
    for (int i = tid; i < F_HID * (F_OUT / 2); i += 256) {
        int r = i >> 4, cp = i & 15;
        float2 w2 = *(const float2*)(W + r * F_OUT + cp * 2);
        *(__half2*)(wh + r * LDW2 + cp * 2) = __floats2half2_rn(w2.x, w2.y);
    }
    // stage h tile (128x64) -> half, padded
    for (int i = tid; i < 128 * (F_HID / 2); i += 256) {
        int r = i >> 5, cp = i & 31;
        float2 h2 = *(const float2*)(g_h + (size_t)(rowb + r) * F_HID + cp * 2);
        *(__half2*)(hh + r * LDX2 + cp * 2) = __floats2half2_rn(h2.x, h2.y);
    }
    __syncthreads();

    int warp = tid >> 5, lane = tid & 31;

    wmma::fragment<wmma::accumulator, 16, 16, 16, float> acc[2];
#pragma unroll
    for (int n = 0; n < 2; n++) wmma::fill_fragment(acc[n], 0.0f);

#pragma unroll
    for (int k = 0; k < 4; k++) {
        wmma::fragment<wmma::matrix_a, 16, 16, 16, __half, wmma::row_major> a;
        wmma::load_matrix_sync(a, hh + (warp * 16) * LDX2 + k * 16, LDX2);
#pragma unroll
        for (int n = 0; n < 2; n++) {
            wmma::fragment<wmma::matrix_b, 16, 16, 16, __half, wmma::row_major> bf;
            wmma::load_matrix_sync(bf, wh + (k * 16) * LDW2 + n * 16, LDW2);
            wmma::mma_sync(acc[n], a, bf, acc[n]);
        }
    }
    __syncthreads();

    float* my = obuf + warp * 16 * LDO2;
#pragma unroll
    for (int n = 0; n < 2; n++)
        wmma::store_matrix_sync(my + n * 16, acc[n], LDO2, wmma::mem_row_major);
    __syncwarp();

#pragma unroll
    for (int i = 0; i < 8; i++) {
        int e = lane + i * 32;      // 0..255 (256 half2 in 16x32 tile)
        int r = e >> 4;             // 16 half2 per row
        int c = e & 15;
        int row = rowb + warp * 16 + r;
        float s = g_dinv[row];
        float lo = my[r * LDO2 + c * 2]     * s;
        float hi = my[r * LDO2 + c * 2 + 1] * s;
        *(__half2*)(g_hws + (size_t)row * F_OUT + c * 2) = __floats2half2_rn(lo, hi);
    }
}

// ---------------- aggregate layer 2 + output epilogue (warp per node) ----------
__global__ void __launch_bounds__(256) k_agg2(const float* __restrict__ b2,
                                              float* __restrict__ out) {
    int node = (blockIdx.x * 256 + threadIdx.x) >> 5;
    int lane = threadIdx.x & 31;
    if (node >= N_NODES) return;

    int k   = g_off[node];
    int end = g_off[node + 1];

    float acc0 = 0.f, acc1 = 0.f;

    for (; k + 8 <= end; k += 8) {
        int idx[8];
#pragma unroll
        for (int j = 0; j < 8; j++) idx[j] = __ldg(g_csr + k + j);
        float v[8];
#pragma unroll
        for (int j = 0; j < 8; j++)
            v[j] = __half2float(g_hws[(size_t)idx[j] * F_OUT + lane]);
        acc0 += (v[0] + v[2]) + (v[4] + v[6]);
        acc1 += (v[1] + v[3]) + (v[5] + v[7]);
    }
    for (; k < end; k++) {
        int s = __ldg(g_csr + k);
        acc0 += __half2float(g_hws[(size_t)s * F_OUT + lane]);
    }

    float self = __half2float(g_hws[(size_t)node * F_OUT + lane]);
    float sc = g_dinv[node];
    out[(size_t)node * F_OUT + lane] = sc * (acc0 + acc1 + self) + b2[lane];
}

// ---------------- launch ----------------
extern "C" void kernel_launch(void* const* d_in, const int* in_sizes, int n_in,
                              void* d_out, int out_size) {
    const float* x  = (const float*)d_in[0];
    const int*   ew = (const int*)d_in[1];
    const float* W1 = (const float*)d_in[2];
    const float* b1 = (const float*)d_in[3];
    const float* W2 = (const float*)d_in[4];
    const float* b2 = (const float*)d_in[5];
    float* out = (float*)d_out;

    const int T = 256;

    k_hist<<<(N_EDGES + T - 1) / T, T>>>(ew);
    k_scan1<<<SCAN_B, 1024>>>();
    k_fill<<<(N_EDGES + T - 1) / T, T>>>(ew);

    k_gemm1<<<(N_NODES + 127) / 128, T>>>(x, W1);
    k_agg1<<<(N_NODES * 32 + T - 1) / T, T>>>(b1);

    k_gemm2<<<(N_NODES + 127) / 128, T>>>(W2);
    k_agg2<<<(N_NODES * 32 + T - 1) / T, T>>>(b2, out);
}

// round 15
// speedup vs baseline: 1.3927x; 1.0919x over previous
#include <cuda_runtime.h>
#include <cuda_fp16.h>
#include <mma.h>
#include <stdint.h>

using namespace nvcuda;

#define N_NODES 100000
#define N_EDGES 1600000
#define F_IN  64
#define F_HID 64
#define F_OUT 32

#define SCAN_B 98   // 98 * 1024 >= N_NODES; single wave on 148 SMs

// ---------------- static device scratch ----------------
__device__ float  g_dinv[N_NODES];
__device__ __half g_xh  [N_NODES * F_IN];    // x converted to fp16 (unscaled)
__device__ __half g_xws [N_NODES * F_HID];   // (x@W1)*dinv, fp16
__device__ __half g_h16 [N_NODES * F_HID];   // relu hidden, fp16
__device__ __half g_hws [N_NODES * F_OUT];   // (h@W2)*dinv, fp16
__device__ int    g_cnt [N_NODES];           // BSS-zero; re-zeroed each call
__device__ int    g_off [N_NODES + 1];
__device__ int    g_cur [N_NODES];
__device__ int    g_csr [N_EDGES];
__device__ int    g_scanval [SCAN_B];
__device__ int    g_scanflag[SCAN_B];
__device__ int    g_done;

// dtype detection: int64 layout (values<2^31) => odd words zero
__device__ __forceinline__ int detect64_t0(const int* __restrict__ w) {
    int nz = 0;
#pragma unroll
    for (int j = 1; j < 16; j += 2) nz |= w[j];
    return nz == 0;
}

// ---------------- histogram over dst + fused x->fp16 conversion ----------------
__global__ void k_hist(const int* __restrict__ ew, const float* __restrict__ x) {
    __shared__ int s64;
    if (threadIdx.x == 0) s64 = detect64_t0(ew);
    __syncthreads();
    int e = blockIdx.x * blockDim.x + threadIdx.x;

    // fused conversion: 1.6M float4 == N_NODES*F_IN/4 exactly
    if (e < N_NODES * F_IN / 4) {
        float4 v = __ldg((const float4*)x + e);
        __half2 h0 = __floats2half2_rn(v.x, v.y);
        __half2 h1 = __floats2half2_rn(v.z, v.w);
        uint2 u;
        u.x = *(unsigned int*)&h0;
        u.y = *(unsigned int*)&h1;
        ((uint2*)g_xh)[e] = u;
    }

    if (e >= N_EDGES) return;
    int d = s64 ? ew[2 * N_EDGES + 2 * e] : ew[N_EDGES + e];
    atomicAdd(&g_cnt[d], 1);
}

// ---------------- single-pass scan ----------------
__global__ void __launch_bounds__(1024) k_scan1() {
    int b = blockIdx.x, t = threadIdx.x;
    int i = b * 1024 + t;
    int lane = t & 31, wid = t >> 5;
    int c = (i < N_NODES) ? g_cnt[i] : 0;

    int inc = c;
#pragma unroll
    for (int o = 1; o < 32; o <<= 1) {
        int u = __shfl_up_sync(0xffffffffu, inc, o);
        if (lane >= o) inc += u;
    }
    __shared__ int wpre[32];
    __shared__ int s_base;
    if (lane == 31) wpre[wid] = inc;
    __syncthreads();

    if (wid == 0) {
        int s = wpre[lane];
        int sinc = s;
#pragma unroll
        for (int o = 1; o < 32; o <<= 1) {
            int u = __shfl_up_sync(0xffffffffu, sinc, o);
            if (lane >= o) sinc += u;
        }
        wpre[lane] = sinc - s;
        if (lane == 31) {
            g_scanval[b] = sinc;
            __threadfence();
            atomicExch(&g_scanflag[b], 1);
        }
    } else if (wid == 1) {
        int base = 0;
        for (int j = lane; j < b; j += 32) {
            while (atomicAdd(&g_scanflag[j], 0) == 0) {}
            __threadfence();
            base += *((volatile int*)(g_scanval + j));
        }
#pragma unroll
        for (int o = 16; o > 0; o >>= 1)
            base += __shfl_down_sync(0xffffffffu, base, o);
        if (lane == 0) s_base = base;
    }
    __syncthreads();

    if (i < N_NODES) {
        int exc = inc - c + wpre[wid] + s_base;
        g_off[i] = exc;
        g_cur[i] = exc;
        g_dinv[i] = rsqrtf((float)c + 1.0f);
        g_cnt[i] = 0;
    }
    if (b == 0 && t == 0) g_off[N_NODES] = N_EDGES;

    __syncthreads();
    if (t == 0) {
        __threadfence();
        int d = atomicAdd(&g_done, 1);
        if (d == gridDim.x - 1) {
            for (int j = 0; j < SCAN_B; j++) g_scanflag[j] = 0;
            g_done = 0;
            __threadfence();
        }
    }
}

// ---------------- fill CSR ----------------
__global__ void k_fill(const int* __restrict__ ew) {
    __shared__ int s64;
    if (threadIdx.x == 0) s64 = detect64_t0(ew);
    __syncthreads();
    int e = blockIdx.x * blockDim.x + threadIdx.x;
    if (e >= N_EDGES) return;
    int s, d;
    if (s64) {
        s = ew[2 * e];
        d = ew[2 * N_EDGES + 2 * e];
    } else {
        s = ew[e];
        d = ew[N_EDGES + e];
    }
    int slot = atomicAdd(&g_cur[d], 1);
    g_csr[slot] = s;
}

// ---------------- GEMM1 (wmma fp16): xws = fp16((x @ W1) * dinv) ----------------
// 8 warps/block, each warp a 16x64 tile; block = 128 rows; A staged from g_xh
#define LDX1 72   // padded half ldm for A tile
#define LDW1 72   // padded half ldm for W1
#define LDO1 68   // padded float ldm for epilogue
__global__ void __launch_bounds__(256) k_gemm1(const float* __restrict__ W) {
    __shared__ __half wh[F_IN * LDW1];                 // 9216 B
    __shared__ float obuf[128 * LDO1];                 // 34816 B (aliases xh)
    __half* xh = (__half*)obuf;                        // 128*LDX1 halves = 18432 B

    int tid = threadIdx.x;
    int rowb = min(blockIdx.x * 128, N_NODES - 128);   // clamped block base

    // stage W1 (64x64) -> half, padded
    for (int i = tid; i < F_IN * (F_HID / 2); i += 256) {
        int r = i >> 5, cp = i & 31;
        float2 w2 = *(const float2*)(W + r * F_HID + cp * 2);
        *(__half2*)(wh + r * LDW1 + cp * 2) = __floats2half2_rn(w2.x, w2.y);
    }
    // stage x half tile (128 rows x 8 uint4), padded
    for (int i = tid; i < 128 * 8; i += 256) {
        int r = i >> 3, c = i & 7;
        uint4 v = *(const uint4*)(g_xh + (size_t)(rowb + r) * F_IN + c * 8);
        *(uint4*)(xh + r * LDX1 + c * 8) = v;
    }
    __syncthreads();

    int warp = tid >> 5, lane = tid & 31;

    wmma::fragment<wmma::accumulator, 16, 16, 16, float> acc[4];
#pragma unroll
    for (int n = 0; n < 4; n++) wmma::fill_fragment(acc[n], 0.0f);

#pragma unroll
    for (int k = 0; k < 4; k++) {
        wmma::fragment<wmma::matrix_a, 16, 16, 16, __half, wmma::row_major> a;
        wmma::load_matrix_sync(a, xh + (warp * 16) * LDX1 + k * 16, LDX1);
#pragma unroll
        for (int n = 0; n < 4; n++) {
            wmma::fragment<wmma::matrix_b, 16, 16, 16, __half, wmma::row_major> bf;
            wmma::load_matrix_sync(bf, wh + (k * 16) * LDW1 + n * 16, LDW1);
            wmma::mma_sync(acc[n], a, bf, acc[n]);
        }
    }
    __syncthreads();   // xh reads complete before obuf overwrite

    float* my = obuf + warp * 16 * LDO1;
#pragma unroll
    for (int n = 0; n < 4; n++)
        wmma::store_matrix_sync(my + n * 16, acc[n], LDO1, wmma::mem_row_major);
    __syncwarp();

#pragma unroll
    for (int r = 0; r < 16; r++) {
        int row = rowb + warp * 16 + r;
        float s = g_dinv[row];
        float lo = my[r * LDO1 + lane * 2]     * s;
        float hi = my[r * LDO1 + lane * 2 + 1] * s;
        *(__half2*)(g_xws + (size_t)row * F_HID + lane * 2) = __floats2half2_rn(lo, hi);
    }
}

// ---------------- aggregate layer 1 + hidden epilogue (warp per node) ----------
__global__ void __launch_bounds__(256) k_agg1(const float* __restrict__ b1) {
    int node = (blockIdx.x * 256 + threadIdx.x) >> 5;
    int lane = threadIdx.x & 31;
    if (node >= N_NODES) return;

    int k   = g_off[node];
    int end = g_off[node + 1];
    int col = lane * 2;

    float2 acc0 = make_float2(0.f, 0.f);
    float2 acc1 = make_float2(0.f, 0.f);

    for (; k + 8 <= end; k += 8) {
        int idx[8];
#pragma unroll
        for (int j = 0; j < 8; j++) idx[j] = __ldg(g_csr + k + j);
        __half2 v[8];
#pragma unroll
        for (int j = 0; j < 8; j++)
            v[j] = *(const __half2*)(g_xws + (size_t)idx[j] * F_HID + col);
#pragma unroll
        for (int j = 0; j < 8; j += 2) {
            float2 f0 = __half22float2(v[j]);
            float2 f1 = __half22float2(v[j + 1]);
            acc0.x += f0.x; acc0.y += f0.y;
            acc1.x += f1.x; acc1.y += f1.y;
        }
    }
    for (; k < end; k++) {
        int s = __ldg(g_csr + k);
        float2 f = __half22float2(*(const __half2*)(g_xws + (size_t)s * F_HID + col));
        acc0.x += f.x; acc0.y += f.y;
    }

    float2 self = __half22float2(*(const __half2*)(g_xws + (size_t)node * F_HID + col));
    float sc = g_dinv[node];
    float2 b = ((const float2*)b1)[lane];
    float rx = fmaxf(sc * (acc0.x + acc1.x + self.x) + b.x, 0.f);
    float ry = fmaxf(sc * (acc0.y + acc1.y + self.y) + b.y, 0.f);
    *(__half2*)(g_h16 + (size_t)node * F_HID + col) = __floats2half2_rn(rx, ry);
}

// ---------------- GEMM2 (wmma fp16): hws = fp16((h @ W2) * dinv) ----------------
#define LDX2 72   // padded half ldm for A tile
#define LDW2 40   // padded half ldm for W2
#define LDO2 36   // padded float ldm for epilogue
__global__ void __launch_bounds__(256) k_gemm2(const float* __restrict__ W) {
    __shared__ __half wh[F_HID * LDW2];                // 5120 B
    __shared__ float obuf[128 * LDO2];                 // 18432 B (aliases hh)
    __half* hh = (__half*)obuf;                        // 128*LDX2 halves = 18432 B

    int tid = threadIdx.x;
    int rowb = min(blockIdx.x * 128, N_NODES - 128);

    // stage W2 (64x32) -> half, padded
    for (int i = tid; i < F_HID * (F_OUT / 2); i += 256) {
        int r = i >> 4, cp = i & 15;
        float2 w2 = *(const float2*)(W + r * F_OUT + cp * 2);
        *(__half2*)(wh + r * LDW2 + cp * 2) = __floats2half2_rn(w2.x, w2.y);
    }
    // stage h half tile (128 rows x 8 uint4), padded
    for (int i = tid; i < 128 * 8; i += 256) {
        int r = i >> 3, c = i & 7;
        uint4 v = *(const uint4*)(g_h16 + (size_t)(rowb + r) * F_HID + c * 8);
        *(uint4*)(hh + r * LDX2 + c * 8) = v;
    }
    __syncthreads();

    int warp = tid >> 5, lane = tid & 31;

    wmma::fragment<wmma::accumulator, 16, 16, 16, float> acc[2];
#pragma unroll
    for (int n = 0; n < 2; n++) wmma::fill_fragment(acc[n], 0.0f);

#pragma unroll
    for (int k = 0; k < 4; k++) {
        wmma::fragment<wmma::matrix_a, 16, 16, 16, __half, wmma::row_major> a;
        wmma::load_matrix_sync(a, hh + (warp * 16) * LDX2 + k * 16, LDX2);
#pragma unroll
        for (int n = 0; n < 2; n++) {
            wmma::fragment<wmma::matrix_b, 16, 16, 16, __half, wmma::row_major> bf;
            wmma::load_matrix_sync(bf, wh + (k * 16) * LDW2 + n * 16, LDW2);
            wmma::mma_sync(acc[n], a, bf, acc[n]);
        }
    }
    __syncthreads();

    float* my = obuf + warp * 16 * LDO2;
#pragma unroll
    for (int n = 0; n < 2; n++)
        wmma::store_matrix_sync(my + n * 16, acc[n], LDO2, wmma::mem_row_major);
    __syncwarp();

#pragma unroll
    for (int i = 0; i < 8; i++) {
        int e = lane + i * 32;      // 0..255 (256 half2 in 16x32 tile)
        int r = e >> 4;             // 16 half2 per row
        int c = e & 15;
        int row = rowb + warp * 16 + r;
        float s = g_dinv[row];
        float lo = my[r * LDO2 + c * 2]     * s;
        float hi = my[r * LDO2 + c * 2 + 1] * s;
        *(__half2*)(g_hws + (size_t)row * F_OUT + c * 2) = __floats2half2_rn(lo, hi);
    }
}

// ---------------- aggregate layer 2 + output epilogue (warp per node) ----------
__global__ void __launch_bounds__(256) k_agg2(const float* __restrict__ b2,
                                              float* __restrict__ out) {
    int node = (blockIdx.x * 256 + threadIdx.x) >> 5;
    int lane = threadIdx.x & 31;
    if (node >= N_NODES) return;

    int k   = g_off[node];
    int end = g_off[node + 1];

    float acc0 = 0.f, acc1 = 0.f;

    for (; k + 8 <= end; k += 8) {
        int idx[8];
#pragma unroll
        for (int j = 0; j < 8; j++) idx[j] = __ldg(g_csr + k + j);
        float v[8];
#pragma unroll
        for (int j = 0; j < 8; j++)
            v[j] = __half2float(g_hws[(size_t)idx[j] * F_OUT + lane]);
        acc0 += (v[0] + v[2]) + (v[4] + v[6]);
        acc1 += (v[1] + v[3]) + (v[5] + v[7]);
    }
    for (; k < end; k++) {
        int s = __ldg(g_csr + k);
        acc0 += __half2float(g_hws[(size_t)s * F_OUT + lane]);
    }

    float self = __half2float(g_hws[(size_t)node * F_OUT + lane]);
    float sc = g_dinv[node];
    out[(size_t)node * F_OUT + lane] = sc * (acc0 + acc1 + self) + b2[lane];
}

// ---------------- launch ----------------
extern "C" void kernel_launch(void* const* d_in, const int* in_sizes, int n_in,
                              void* d_out, int out_size) {
    const float* x  = (const float*)d_in[0];
    const int*   ew = (const int*)d_in[1];
    const float* W1 = (const float*)d_in[2];
    const float* b1 = (const float*)d_in[3];
    const float* W2 = (const float*)d_in[4];
    const float* b2 = (const float*)d_in[5];
    float* out = (float*)d_out;

    const int T = 256;

    k_hist<<<(N_EDGES + T - 1) / T, T>>>(ew, x);
    k_scan1<<<SCAN_B, 1024>>>();
    k_fill<<<(N_EDGES + T - 1) / T, T>>>(ew);

    k_gemm1<<<(N_NODES + 127) / 128, T>>>(W1);
    k_agg1<<<(N_NODES * 32 + T - 1) / T, T>>>(b1);

    k_gemm2<<<(N_NODES + 127) / 128, T>>>(W2);
    k_agg2<<<(N_NODES * 32 + T - 1) / T, T>>>(b2, out);
}